// round 12
// baseline (speedup 1.0000x reference)
#include <cuda_runtime.h>
#include <cstdint>

#define SGX 32
#define SGY 24
#define SGT 5
#define NBINS (2 * SGT * SGY * SGX)   // 7680

#define GRID     296
#define THREADS  1024
#define HALFG    148                  // classic placement: SM = LUT[bid % 148]
#define PSM      74                   // SM slots [0,74) = producers, [74,148) = consumers

#define N_MAX    16777216
#define CH       16384                // events per chunk
#define NCHUNK_MAX (N_MAX / CH)       // 1024

#define TQ_MAXI   2097151u
#define TQ_SCALE  (2097151.0f / 50.0f)   // t in [0,50] -> [0, 2^21-1]
#define C_FIXED   (5.0f / 2097152.0f)    // exact 5*2^-21 (product is exact in f32)
#define GUARD_U   1280u                  // guard band in u = 5*tq space
#define CHECK_DEV 1000ll                 // |5*bk - k*2^21| must be <= this (< GUARD_U)
#define BUF_CAP   (1u << 20)             // 4 MB side buffer (expected ~16k entries)

__device__ uint32_t     g_code[N_MAX / 2];     // 32 MB: 2 x u16 speculative bins / word
__device__ uint32_t     g_buf[BUF_CAP];        // near-boundary packed records
__device__ unsigned int g_counts[NBINS];       // fast-path histogram
__device__ unsigned int g_counts2[NBINS];      // slow-path histogram
__device__ unsigned int g_qmin = 0xFFFFFFFFu;  // reset by finalizer
__device__ unsigned int g_qmax = 0u;
__device__ unsigned int g_ready[NCHUNK_MAX];   // per-chunk produced flags
__device__ unsigned int g_pt, g_ct, g_bufcnt, g_arrive, g_exit;

// decode -> u16 speculative code (0xFFFF sentinel if near a fixed threshold),
// quantized t, packed record (p<<10|yv<<5|xv)<<21 | tq
__device__ __forceinline__ unsigned int decode(float4 e, unsigned int& tq,
                                               uint32_t& rec, bool& bdry) {
    int xv = min(max((int)(e.x * 0.05f), 0), SGX - 1);
    int yv = min(max((int)(e.y * 0.05f), 0), SGY - 1);
    float tf = fmaxf(fmaf(e.z, TQ_SCALE, 0.5f), 0.0f);
    tq = min((unsigned int)tf, TQ_MAXI);
    unsigned int p = (e.w > 0.0f) ? 0u : 1u;
    unsigned int sp = p * 3840u + (unsigned int)yv * 32u + (unsigned int)xv;
    unsigned int u = tq * 5u;
    bdry = ((u + GUARD_U) & 0x1FFFFFu) < 2u * GUARD_U;
    int tv = (int)((float)tq * C_FIXED);            // exact floor(5*tq/2^21)
    rec = (((p << 10) | ((unsigned int)yv << 5) | (unsigned int)xv) << 21) | tq;
    return bdry ? 0xFFFFu : ((unsigned int)tv * 768u + sp);
}

__device__ __forceinline__ void buf_append(bool pred, uint32_t rec) {
    unsigned int mask = __ballot_sync(__activemask(), pred);
    if (!pred) return;
    int leader = __ffs(mask) - 1;
    int lane   = threadIdx.x & 31;
    unsigned int base = 0;
    if (lane == leader) base = atomicAdd(&g_bufcnt, (unsigned int)__popc(mask));
    base = __shfl_sync(mask, base, leader);
    unsigned int idx = base + (unsigned int)__popc(mask & ((1u << lane) - 1u));
    if (idx < BUF_CAP) g_buf[idx] = rec;
}

__global__ __launch_bounds__(THREADS, 2)
void voxel_kernel(const float4* __restrict__ ev, int n, int nchunk,
                  float* __restrict__ out, float inv_s) {
    __shared__ unsigned int sh[NBINS];
    __shared__ unsigned int smin[32], smax[32];
    __shared__ int s_chunk;
    __shared__ unsigned int s_b1, s_b2, s_b3, s_b4, s_cnt;
    __shared__ int s_fast;
    __shared__ bool s_last;

    const int tid = threadIdx.x;
    const bool producer = (blockIdx.x % HALFG) < PSM;

    if (producer) {
        // =================== PRODUCER: stream + pack ===================
        unsigned int tqmin = 0xFFFFFFFFu, tqmax = 0u;
        while (true) {
            __syncthreads();
            if (tid == 0) s_chunk = (int)atomicAdd(&g_pt, 1u);
            __syncthreads();
            int c = s_chunk;
            if (c >= nchunk) break;
            int e0 = c * CH;
            int e1 = min(n, e0 + CH);
            int w0 = e0 >> 1;
            int w1 = (e1 + 1) >> 1;
            for (int w = w0 + tid; w < w1; w += THREADS) {
                int i0 = 2 * w;
                float4 ea = __ldcs(ev + i0);
                unsigned int tqa; uint32_t ra; bool ba;
                unsigned int ca = decode(ea, tqa, ra, ba);
                tqmin = min(tqmin, tqa); tqmax = max(tqmax, tqa);
                buf_append(ba, ra);
                unsigned int cb = 0xFFFFu;
                if (i0 + 1 < e1) {
                    float4 eb = __ldcs(ev + i0 + 1);
                    unsigned int tqb; uint32_t rb; bool bb;
                    cb = decode(eb, tqb, rb, bb);
                    tqmin = min(tqmin, tqb); tqmax = max(tqmax, tqb);
                    buf_append(bb, rb);
                }
                g_code[w] = ca | (cb << 16);
            }
            __threadfence();           // publish this chunk's codes (every thread)
            __syncthreads();
            if (tid == 0) atomicExch(&g_ready[c], 1u);
        }
        // block-reduce qmin/qmax -> global
        #pragma unroll
        for (int o = 16; o > 0; o >>= 1) {
            tqmin = min(tqmin, __shfl_xor_sync(0xFFFFFFFFu, tqmin, o));
            tqmax = max(tqmax, __shfl_xor_sync(0xFFFFFFFFu, tqmax, o));
        }
        int wid = tid >> 5, lid = tid & 31;
        if (lid == 0) { smin[wid] = tqmin; smax[wid] = tqmax; }
        __syncthreads();
        if (tid == 0) {
            int nw = THREADS >> 5;
            unsigned int m0 = smin[0], m1 = smax[0];
            for (int w = 1; w < nw; w++) { m0 = min(m0, smin[w]); m1 = max(m1, smax[w]); }
            atomicMin(&g_qmin, m0);
            atomicMax(&g_qmax, m1);
        }
    } else {
        // =================== CONSUMER: histogram ===================
        for (int b = tid; b < NBINS; b += THREADS) sh[b] = 0u;
        while (true) {
            __syncthreads();
            if (tid == 0) s_chunk = (int)atomicAdd(&g_ct, 1u);
            __syncthreads();
            int c = s_chunk;
            if (c >= nchunk) break;
            if (tid == 0) {
                volatile unsigned int* vr = &g_ready[c];
                while (*vr == 0u) __nanosleep(128);
                __threadfence();
            }
            __syncthreads();
            int e0 = c * CH;
            int e1 = min(n, e0 + CH);
            int w0 = e0 >> 1;                    // divisible by 4 (CH/2 = 8192)
            int w1 = (e1 + 1) >> 1;
            int nq = (w1 - w0) >> 2;
            const uint4* p4 = reinterpret_cast<const uint4*>(g_code + w0);
            for (int q = tid; q < nq; q += THREADS) {
                uint4 a = __ldcg(p4 + q);
                #pragma unroll
                for (int k = 0; k < 4; k++) {
                    unsigned int w = (&a.x)[k];
                    unsigned int v0 = w & 0xFFFFu, v1 = w >> 16;
                    if (v0 != 0xFFFFu) atomicAdd(&sh[v0], 1u);
                    if (v1 != 0xFFFFu) atomicAdd(&sh[v1], 1u);
                }
            }
            for (int w = w0 + (nq << 2) + tid; w < w1; w += THREADS) {
                unsigned int x = __ldcg(g_code + w);
                unsigned int v0 = x & 0xFFFFu, v1 = x >> 16;
                if (v0 != 0xFFFFu) atomicAdd(&sh[v0], 1u);
                if (v1 != 0xFFFFu) atomicAdd(&sh[v1], 1u);
            }
        }
        __syncthreads();
        for (int b = tid; b < NBINS; b += THREADS) {
            unsigned int v = sh[b];
            if (v) atomicAdd(&g_counts[b], v);
        }
    }

    // =================== grid barrier (all 296 CTAs resident) ===================
    __threadfence();
    __syncthreads();
    if (tid == 0) {
        atomicAdd(&g_arrive, 1u);
        volatile unsigned int* va = &g_arrive;
        while (*va < (unsigned int)GRID) __nanosleep(64);
        __threadfence();
    }
    __syncthreads();

    // exact thresholds + fast/slow decision (redundant per block)
    if (tid == 0) {
        unsigned int m0 = *(volatile unsigned int*)&g_qmin;
        unsigned int m1 = *(volatile unsigned int*)&g_qmax;
        int fast = 1;
        unsigned int b1, b2, b3, b4;
        if (m1 > m0) {
            unsigned long long range = (unsigned long long)(m1 - m0);
            unsigned long long bk;
            long long dev;
            bk = (unsigned long long)m0 + (1ull * range + 4ull) / 5ull;
            dev = (long long)(5ull * bk) - (long long)(1ull << 21) * 1ll;
            if (dev < -CHECK_DEV || dev > CHECK_DEV) fast = 0;  b1 = (unsigned int)bk;
            bk = (unsigned long long)m0 + (2ull * range + 4ull) / 5ull;
            dev = (long long)(5ull * bk) - (long long)(1ull << 21) * 2ll;
            if (dev < -CHECK_DEV || dev > CHECK_DEV) fast = 0;  b2 = (unsigned int)bk;
            bk = (unsigned long long)m0 + (3ull * range + 4ull) / 5ull;
            dev = (long long)(5ull * bk) - (long long)(1ull << 21) * 3ll;
            if (dev < -CHECK_DEV || dev > CHECK_DEV) fast = 0;  b3 = (unsigned int)bk;
            bk = (unsigned long long)m0 + (4ull * range + 4ull) / 5ull;
            dev = (long long)(5ull * bk) - (long long)(1ull << 21) * 4ll;
            if (dev < -CHECK_DEV || dev > CHECK_DEV) fast = 0;  b4 = (unsigned int)bk;
        } else {
            // degenerate: raw-t thresholds ceil(k*10*TQ_SCALE); dev ~ +3
            b1 = 419431u; b2 = 838861u; b3 = 1258291u; b4 = 1677721u;
        }
        unsigned int bc = *(volatile unsigned int*)&g_bufcnt;
        if (bc > BUF_CAP) fast = 0;
        s_b1 = b1; s_b2 = b2; s_b3 = b3; s_b4 = b4;
        s_cnt = min(bc, BUF_CAP);
        s_fast = fast;
    }
    __syncthreads();
    unsigned int b1 = s_b1, b2 = s_b2, b3 = s_b3, b4 = s_b4;
    int gstride = GRID * THREADS;
    int gbase = blockIdx.x * THREADS + tid;

    if (s_fast) {
        // fixup buffered boundary events with exact thresholds (all blocks)
        int cnt = (int)s_cnt;
        for (int j = gbase; j < cnt; j += gstride) {
            uint32_t r = g_buf[j];
            unsigned int tq = r & 0x1FFFFFu;
            int tv = (int)(tq >= b1) + (int)(tq >= b2) + (int)(tq >= b3) + (int)(tq >= b4);
            unsigned int s = r >> 21;
            int sp = (int)((s >> 10) * 3840u) + (int)(s & 1023u);
            atomicAdd(&g_counts[tv * 768 + sp], 1u);
        }
    } else {
        // slow path: exact re-histogram from original events (all blocks)
        for (int b = tid; b < NBINS; b += THREADS) sh[b] = 0u;
        __syncthreads();
        for (int i = gbase; i < n; i += gstride) {
            float4 e = __ldcs(ev + i);
            unsigned int tq; uint32_t r; bool bd;
            (void)decode(e, tq, r, bd);
            int tv = (int)(tq >= b1) + (int)(tq >= b2) + (int)(tq >= b3) + (int)(tq >= b4);
            unsigned int s = r >> 21;
            int sp = (int)((s >> 10) * 3840u) + (int)(s & 1023u);
            atomicAdd(&sh[tv * 768 + sp], 1u);
        }
        __syncthreads();
        for (int b = tid; b < NBINS; b += THREADS) {
            unsigned int v = sh[b];
            if (v) atomicAdd(&g_counts2[b], v);
        }
    }

    // =================== exit counter + finalize + state reset ===================
    __threadfence();
    __syncthreads();
    if (tid == 0) {
        unsigned int t = atomicAdd(&g_exit, 1u);
        s_last = (t == (unsigned int)GRID - 1u);
    }
    __syncthreads();
    if (s_last) {
        __threadfence();
        int fast = s_fast;
        for (int b = tid; b < NBINS; b += THREADS) {
            unsigned int c = fast ? g_counts[b] : g_counts2[b];
            out[b] = (float)c * inv_s;
            g_counts[b]  = 0u;
            g_counts2[b] = 0u;
        }
        for (int c = tid; c < nchunk; c += THREADS) g_ready[c] = 0u;
        if (tid == 0) {
            g_pt = 0u; g_ct = 0u; g_bufcnt = 0u;
            g_qmin = 0xFFFFFFFFu; g_qmax = 0u;
            g_arrive = 0u; g_exit = 0u;
            __threadfence();
        }
    }
}

extern "C" void kernel_launch(void* const* d_in, const int* in_sizes, int n_in,
                              void* d_out, int out_size) {
    const float4* ev = (const float4*)d_in[0];
    int n = in_sizes[0] / 4;              // events: (N, 4) f32, N = 2^24
    float* out = (float*)d_out;

    int nchunk = (n + CH - 1) / CH;
    float inv_s = (n > 0) ? (1.0f / (float)n) : 1.0f;

    voxel_kernel<<<GRID, THREADS>>>(ev, n, nchunk, out, inv_s);
}

// round 13
// speedup vs baseline: 1.3822x; 1.3822x over previous
#include <cuda_runtime.h>
#include <cstdint>

#define SGX 32
#define SGY 24
#define SGT 5
#define NBINS (2 * SGT * SGY * SGX)   // 7680

#define BLOCKS   296
#define THREADS1 512                  // pass1: R8 geometry (47.3us baseline)
#define THREADS2 1024                 // pass2: full occupancy (22.7us baseline)

#define N_MAX    16777216
#define TQ_MAXI   2097151u
#define TQ_SCALE  (2097151.0f / 50.0f)   // t in [0,50] -> [0, 2^21-1]
#define C_FIXED   (5.0f / 2097152.0f)    // exact 5*2^-21; tq*C_FIXED exact in f32
#define GUARD_U   1280u                  // guard band in u = 5*tq space
#define CHECK_DEV 1000ll                 // |5*bk - k*2^21| <= this  (< GUARD_U)
#define SENT      0xFFFFu

__device__ uint32_t     g_code[N_MAX / 2 + 1];  // 32 MB: 2 x u16 bins per word
__device__ unsigned int g_counts[NBINS];        // fast-path histogram
__device__ unsigned int g_counts2[NBINS];       // slow-path histogram
__device__ unsigned int g_bqmin[BLOCKS];
__device__ unsigned int g_bqmax[BLOCKS];
__device__ unsigned int g_done;

// decode -> u16 speculative bin code (SENT if within guard band of a fixed
// threshold k*2^21/5), and quantized t
__device__ __forceinline__ unsigned int decode_code(float4 e, unsigned int& tq) {
    int xv = min(max((int)(e.x * 0.05f), 0), SGX - 1);
    int yv = min(max((int)(e.y * 0.05f), 0), SGY - 1);
    float tf = fmaxf(fmaf(e.z, TQ_SCALE, 0.5f), 0.0f);
    tq = min((unsigned int)tf, TQ_MAXI);
    unsigned int p = (e.w > 0.0f) ? 0u : 1u;
    unsigned int sp = p * 3840u + (unsigned int)yv * 32u + (unsigned int)xv;
    unsigned int u = tq * 5u;
    bool bdry = ((u + GUARD_U) & 0x1FFFFFu) < 2u * GUARD_U;
    int tv = (int)((float)tq * C_FIXED);            // exact floor(5*tq/2^21)
    return bdry ? SENT : ((unsigned int)tv * 768u + sp);
}

// exact-threshold bin from a raw event (used for sentinel fixup + slow path)
__device__ __forceinline__ int bin_exact(float4 e, unsigned int b1, unsigned int b2,
                                         unsigned int b3, unsigned int b4) {
    int xv = min(max((int)(e.x * 0.05f), 0), SGX - 1);
    int yv = min(max((int)(e.y * 0.05f), 0), SGY - 1);
    float tf = fmaxf(fmaf(e.z, TQ_SCALE, 0.5f), 0.0f);
    unsigned int tq = min((unsigned int)tf, TQ_MAXI);
    unsigned int p = (e.w > 0.0f) ? 0u : 1u;
    int tv = (int)(tq >= b1) + (int)(tq >= b2) + (int)(tq >= b3) + (int)(tq >= b4);
    return tv * 768 + (int)(p * 3840u) + yv * SGX + xv;
}

// ---------------------------------------------------------------------------
// Pass 1: stream events (evict-first), emit packed u16 speculative bins,
// per-block qmin/qmax partials; zero accumulators + done flag.
// ---------------------------------------------------------------------------
__global__ __launch_bounds__(THREADS1, 2)
void pass1_kernel(const float4* __restrict__ ev, int n) {
    int gtid = blockIdx.x * blockDim.x + threadIdx.x;
    int stride = gridDim.x * blockDim.x;
    for (int b = gtid; b < NBINS; b += stride) { g_counts[b] = 0u; g_counts2[b] = 0u; }
    if (gtid == 0) g_done = 0u;

    unsigned int tqmin = 0xFFFFFFFFu;
    unsigned int tqmax = 0u;
    int nw = n >> 1;                      // whole words (2 events each)
    int w = gtid;

    for (; w + 3 * stride < nw; w += 4 * stride) {
        int w1 = w + stride, w2 = w + 2 * stride, w3 = w + 3 * stride;
        float4 ea0 = __ldcs(ev + 2 * w);      float4 eb0 = __ldcs(ev + 2 * w + 1);
        float4 ea1 = __ldcs(ev + 2 * w1);     float4 eb1 = __ldcs(ev + 2 * w1 + 1);
        float4 ea2 = __ldcs(ev + 2 * w2);     float4 eb2 = __ldcs(ev + 2 * w2 + 1);
        float4 ea3 = __ldcs(ev + 2 * w3);     float4 eb3 = __ldcs(ev + 2 * w3 + 1);
        unsigned int ta0, tb0, ta1, tb1, ta2, tb2, ta3, tb3;
        unsigned int c;
        c = decode_code(ea0, ta0) | (decode_code(eb0, tb0) << 16);  g_code[w]  = c;
        c = decode_code(ea1, ta1) | (decode_code(eb1, tb1) << 16);  g_code[w1] = c;
        c = decode_code(ea2, ta2) | (decode_code(eb2, tb2) << 16);  g_code[w2] = c;
        c = decode_code(ea3, ta3) | (decode_code(eb3, tb3) << 16);  g_code[w3] = c;
        tqmin = min(tqmin, min(min(ta0, tb0), min(ta1, tb1)));
        tqmin = min(tqmin, min(min(ta2, tb2), min(ta3, tb3)));
        tqmax = max(tqmax, max(max(ta0, tb0), max(ta1, tb1)));
        tqmax = max(tqmax, max(max(ta2, tb2), max(ta3, tb3)));
    }
    #pragma unroll 1
    for (; w < nw; w += stride) {
        float4 ea = __ldcs(ev + 2 * w);
        float4 eb = __ldcs(ev + 2 * w + 1);
        unsigned int ta, tb;
        g_code[w] = decode_code(ea, ta) | (decode_code(eb, tb) << 16);
        tqmin = min(tqmin, min(ta, tb));
        tqmax = max(tqmax, max(ta, tb));
    }
    // odd tail event
    if (gtid == 0 && (n & 1)) {
        float4 e = __ldcs(ev + (n - 1));
        unsigned int t;
        unsigned int c = decode_code(e, t);
        g_code[n >> 1] = c | (SENT << 16) ^ (SENT << 16);  // low half only
        g_code[n >> 1] = c;                                 // (store code in low half)
        tqmin = min(tqmin, t);
        tqmax = max(tqmax, t);
    }

    // block minmax reduce -> per-block partials
    #pragma unroll
    for (int o = 16; o > 0; o >>= 1) {
        tqmin = min(tqmin, __shfl_xor_sync(0xFFFFFFFFu, tqmin, o));
        tqmax = max(tqmax, __shfl_xor_sync(0xFFFFFFFFu, tqmax, o));
    }
    __shared__ unsigned int smin[16], smax[16];
    int wid = threadIdx.x >> 5;
    int lid = threadIdx.x & 31;
    if (lid == 0) { smin[wid] = tqmin; smax[wid] = tqmax; }
    __syncthreads();
    if (wid == 0) {
        int nwarp = blockDim.x >> 5;
        tqmin = (lid < nwarp) ? smin[lid] : 0xFFFFFFFFu;
        tqmax = (lid < nwarp) ? smax[lid] : 0u;
        #pragma unroll
        for (int o = 8; o > 0; o >>= 1) {
            tqmin = min(tqmin, __shfl_xor_sync(0xFFFFFFFFu, tqmin, o));
            tqmax = max(tqmax, __shfl_xor_sync(0xFFFFFFFFu, tqmax, o));
        }
        if (lid == 0) {
            g_bqmin[blockIdx.x] = tqmin;
            g_bqmax[blockIdx.x] = tqmax;
        }
    }
}

// ---------------------------------------------------------------------------
// Pass 2: exact thresholds; fast path = histogram u16 codes (L2-resident)
// with inline sentinel fixup from ev; slow path = exact re-histogram.
// ---------------------------------------------------------------------------
__global__ __launch_bounds__(THREADS2, 2)
void pass2_kernel(const float4* __restrict__ ev, int n,
                  float* __restrict__ out, float inv_s) {
    __shared__ unsigned int sh[NBINS];
    __shared__ unsigned int wmin[32], wmax[32];
    __shared__ unsigned int s_b[5];
    __shared__ int s_fast;
    __shared__ bool s_last;

    for (int b = threadIdx.x; b < NBINS; b += blockDim.x) sh[b] = 0u;

    // reduce per-block partials
    unsigned int tqmin = 0xFFFFFFFFu, tqmax = 0u;
    for (int b = threadIdx.x; b < BLOCKS; b += blockDim.x) {
        tqmin = min(tqmin, g_bqmin[b]);
        tqmax = max(tqmax, g_bqmax[b]);
    }
    #pragma unroll
    for (int o = 16; o > 0; o >>= 1) {
        tqmin = min(tqmin, __shfl_xor_sync(0xFFFFFFFFu, tqmin, o));
        tqmax = max(tqmax, __shfl_xor_sync(0xFFFFFFFFu, tqmax, o));
    }
    int wid = threadIdx.x >> 5;
    int lid = threadIdx.x & 31;
    if (lid == 0) { wmin[wid] = tqmin; wmax[wid] = tqmax; }
    __syncthreads();
    if (threadIdx.x == 0) {
        int nwarp = blockDim.x >> 5;
        unsigned int m0 = wmin[0], m1 = wmax[0];
        for (int w = 1; w < nwarp; w++) { m0 = min(m0, wmin[w]); m1 = max(m1, wmax[w]); }
        int fast = 1;
        if (m1 > m0) {
            unsigned long long range = (unsigned long long)(m1 - m0);
            for (unsigned long long k = 1; k <= 4; k++) {
                unsigned long long bk = (unsigned long long)m0 + (k * range + 4ull) / 5ull;
                long long dev = (long long)(5ull * bk) - (long long)(k << 21);
                if (dev < -CHECK_DEV || dev > CHECK_DEV) fast = 0;
                s_b[k] = (unsigned int)bk;
            }
        } else {
            // degenerate: raw-t thresholds ceil(k*10*TQ_SCALE); dev ~= +3..+12
            s_b[1] = 419431u;  s_b[2] = 838861u;
            s_b[3] = 1258291u; s_b[4] = 1677721u;
        }
        s_fast = fast;
    }
    __syncthreads();
    unsigned int b1 = s_b[1], b2 = s_b[2], b3 = s_b[3], b4 = s_b[4];

    int stride = gridDim.x * blockDim.x;

    if (s_fast) {
        // ---- fast path: u16 codes, 2 x uint4 per iter (16 events) ----
        const uint4* pk4 = reinterpret_cast<const uint4*>(g_code);
        int nwords = (n + 1) >> 1;
        int nq = nwords >> 2;                     // uint4 count (8 events each)
        int i = blockIdx.x * blockDim.x + threadIdx.x;
        for (; i + stride < nq; i += 2 * stride) {
            uint4 a = pk4[i];
            uint4 b = pk4[i + stride];
            #pragma unroll
            for (int k = 0; k < 4; k++) {
                unsigned int wv = (&a.x)[k];
                unsigned int v0 = wv & 0xFFFFu, v1 = wv >> 16;
                if (v0 != SENT) atomicAdd(&sh[v0], 1u);
                else atomicAdd(&sh[bin_exact(__ldcs(ev + 2 * (4 * i + k)), b1, b2, b3, b4)], 1u);
                if (v1 != SENT) atomicAdd(&sh[v1], 1u);
                else atomicAdd(&sh[bin_exact(__ldcs(ev + 2 * (4 * i + k) + 1), b1, b2, b3, b4)], 1u);
            }
            int ib = i + stride;
            #pragma unroll
            for (int k = 0; k < 4; k++) {
                unsigned int wv = (&b.x)[k];
                unsigned int v0 = wv & 0xFFFFu, v1 = wv >> 16;
                if (v0 != SENT) atomicAdd(&sh[v0], 1u);
                else atomicAdd(&sh[bin_exact(__ldcs(ev + 2 * (4 * ib + k)), b1, b2, b3, b4)], 1u);
                if (v1 != SENT) atomicAdd(&sh[v1], 1u);
                else atomicAdd(&sh[bin_exact(__ldcs(ev + 2 * (4 * ib + k) + 1), b1, b2, b3, b4)], 1u);
            }
        }
        #pragma unroll 1
        for (; i < nq; i += stride) {
            uint4 a = pk4[i];
            #pragma unroll
            for (int k = 0; k < 4; k++) {
                unsigned int wv = (&a.x)[k];
                unsigned int v0 = wv & 0xFFFFu, v1 = wv >> 16;
                if (v0 != SENT) atomicAdd(&sh[v0], 1u);
                else atomicAdd(&sh[bin_exact(__ldcs(ev + 2 * (4 * i + k)), b1, b2, b3, b4)], 1u);
                if (v1 != SENT) atomicAdd(&sh[v1], 1u);
                else atomicAdd(&sh[bin_exact(__ldcs(ev + 2 * (4 * i + k) + 1), b1, b2, b3, b4)], 1u);
            }
        }
        // tail events beyond 8*nq
        #pragma unroll 1
        for (int j = (nq << 3) + blockIdx.x * blockDim.x + threadIdx.x; j < n; j += stride) {
            unsigned int v = reinterpret_cast<const unsigned short*>(g_code)[j];
            if (v != SENT) atomicAdd(&sh[v], 1u);
            else atomicAdd(&sh[bin_exact(__ldcs(ev + j), b1, b2, b3, b4)], 1u);
        }
        __syncthreads();
        for (int b = threadIdx.x; b < NBINS; b += blockDim.x) {
            unsigned int v = sh[b];
            if (v) atomicAdd(&g_counts[b], v);
        }
    } else {
        // ---- slow path: exact re-histogram from original events ----
        for (int i = blockIdx.x * blockDim.x + threadIdx.x; i < n; i += stride) {
            atomicAdd(&sh[bin_exact(__ldcs(ev + i), b1, b2, b3, b4)], 1u);
        }
        __syncthreads();
        for (int b = threadIdx.x; b < NBINS; b += blockDim.x) {
            unsigned int v = sh[b];
            if (v) atomicAdd(&g_counts2[b], v);
        }
    }

    // ---- last-block finalize ----
    __threadfence();
    __syncthreads();
    if (threadIdx.x == 0) {
        unsigned int t = atomicAdd(&g_done, 1u);
        s_last = (t == gridDim.x - 1);
    }
    __syncthreads();
    if (s_last) {
        __threadfence();
        int fast = s_fast;
        for (int b = threadIdx.x; b < NBINS; b += blockDim.x) {
            unsigned int c = fast ? g_counts[b] : g_counts2[b];
            out[b] = (float)c * inv_s;
        }
    }
}

extern "C" void kernel_launch(void* const* d_in, const int* in_sizes, int n_in,
                              void* d_out, int out_size) {
    const float4* ev = (const float4*)d_in[0];
    int n = in_sizes[0] / 4;              // events: (N, 4) f32, N = 2^24
    float* out = (float*)d_out;

    // every event lands in exactly one bin -> grid.sum() == N exactly
    float inv_s = (n > 0) ? (1.0f / (float)n) : 1.0f;

    pass1_kernel<<<BLOCKS, THREADS1>>>(ev, n);
    pass2_kernel<<<BLOCKS, THREADS2>>>(ev, n, out, inv_s);
}